// round 2
// baseline (speedup 1.0000x reference)
#include <cuda_runtime.h>
#include <math.h>

#define LQ 8192
#define HD 1024
#define PD 1024
#define N1 2048      // 2P: [re | im] width
#define NCHUNK 128
#define CHUNK 64

// ---------------- scratch (device globals; no runtime allocation) ----------------
__device__ float g_Bbar[N1 * HD];        // (2P, H): rows 0..P-1 = re, P..2P-1 = im
__device__ float g_Cfused[HD * N1];      // (H, 2P): [C_re | -C_im]
__device__ float g_Bu[LQ * N1];          // (L, 2P): per row [re(0:P) | im(P:2P)]
__device__ float g_xs[LQ * N1];          // scan output, same layout
__device__ float g_Abar_re[PD], g_Abar_im[PD];
__device__ float g_coef_re[PD], g_coef_im[PD];
__device__ float g_AS_re[PD],   g_AS_im[PD];       // Abar^CHUNK
__device__ float g_E_re[NCHUNK * PD], g_E_im[NCHUNK * PD];
__device__ float g_pref_re[NCHUNK * PD], g_pref_im[NCHUNK * PD];

// ---------------- setup: discretization (fp64 for stability near |A|->1) ----------------
__global__ void setup_kernel(const float* __restrict__ Lre, const float* __restrict__ Lim,
                             const float* __restrict__ logdt)
{
    int p = blockIdx.x * blockDim.x + threadIdx.x;
    if (p >= PD) return;
    double dt  = exp((double)logdt[p]);
    double lr  = (double)Lre[p], li = (double)Lim[p];
    double mag = exp(lr * dt);
    double ang = li * dt;
    double ar  = mag * cos(ang);
    double ai  = mag * sin(ang);
    double den = lr * lr + li * li;
    double cr  = ((ar - 1.0) * lr + ai * li) / den;
    double ci  = (ai * lr - (ar - 1.0) * li) / den;
    g_Abar_re[p] = (float)ar; g_Abar_im[p] = (float)ai;
    g_coef_re[p] = (float)cr; g_coef_im[p] = (float)ci;
    double sr = ar, si = ai;
    #pragma unroll
    for (int i = 0; i < 6; i++) {   // Abar^64 via 6 squarings
        double nr = sr * sr - si * si;
        double ni = 2.0 * sr * si;
        sr = nr; si = ni;
    }
    g_AS_re[p] = (float)sr; g_AS_im[p] = (float)si;
}

__global__ void build_bbar(const float* __restrict__ Bre, const float* __restrict__ Bim)
{
    int idx = blockIdx.x * blockDim.x + threadIdx.x;   // idx = p*H + h
    if (idx >= PD * HD) return;
    int p = idx >> 10;
    float br = Bre[idx], bi = Bim[idx];
    float cr = g_coef_re[p], ci = g_coef_im[p];
    g_Bbar[idx]            = cr * br - ci * bi;   // row p      (re part)
    g_Bbar[PD * HD + idx]  = cr * bi + ci * br;   // row P + p  (im part)
}

__global__ void build_cfused(const float* __restrict__ Cre, const float* __restrict__ Cim)
{
    int idx = blockIdx.x * blockDim.x + threadIdx.x;   // idx = h*P + p
    if (idx >= HD * PD) return;
    int h = idx >> 10, p = idx & (PD - 1);
    g_Cfused[h * N1 + p]       =  Cre[idx];
    g_Cfused[h * N1 + PD + p]  = -Cim[idx];
}

// ---------------- SGEMM (NT, row-major, K-contig both sides) ----------------
// C[M,N] = A[M,K] @ B[N,K]^T. BM=BN=128, BK=8, 256 threads, 8x8 microtile.
template<bool EPI>
__device__ __forceinline__ void sgemm_body(const float* __restrict__ A, const float* __restrict__ B,
                                           float* __restrict__ C, int K, int N,
                                           const float* __restrict__ xres, const float* __restrict__ Dp)
{
    __shared__ float As[8][128];
    __shared__ float Bs[8][128];
    const int tid = threadIdx.x;
    const int bm = blockIdx.y * 128;
    const int bn = blockIdx.x * 128;
    const int lr = tid >> 1;           // load row within tile (0..127)
    const int lc = (tid & 1) << 2;     // 0 or 4
    const float* Ag = A + (size_t)(bm + lr) * K + lc;
    const float* Bg = B + (size_t)(bn + lr) * K + lc;
    const int ty = tid >> 4, tx = tid & 15;

    float acc[8][8];
    #pragma unroll
    for (int i = 0; i < 8; i++)
        #pragma unroll
        for (int j = 0; j < 8; j++) acc[i][j] = 0.f;

    for (int k0 = 0; k0 < K; k0 += 8) {
        float4 av = *(const float4*)(Ag + k0);
        float4 bv = *(const float4*)(Bg + k0);
        As[lc + 0][lr] = av.x; As[lc + 1][lr] = av.y; As[lc + 2][lr] = av.z; As[lc + 3][lr] = av.w;
        Bs[lc + 0][lr] = bv.x; Bs[lc + 1][lr] = bv.y; Bs[lc + 2][lr] = bv.z; Bs[lc + 3][lr] = bv.w;
        __syncthreads();
        #pragma unroll
        for (int kk = 0; kk < 8; kk++) {
            float a[8], b[8];
            *(float4*)(a)     = *(const float4*)&As[kk][ty * 8];
            *(float4*)(a + 4) = *(const float4*)&As[kk][ty * 8 + 4];
            *(float4*)(b)     = *(const float4*)&Bs[kk][tx * 8];
            *(float4*)(b + 4) = *(const float4*)&Bs[kk][tx * 8 + 4];
            #pragma unroll
            for (int i = 0; i < 8; i++)
                #pragma unroll
                for (int j = 0; j < 8; j++)
                    acc[i][j] = fmaf(a[i], b[j], acc[i][j]);
        }
        __syncthreads();
    }

    #pragma unroll
    for (int i = 0; i < 8; i++) {
        int row = bm + ty * 8 + i;
        #pragma unroll
        for (int j = 0; j < 8; j += 4) {
            int col = bn + tx * 8 + j;
            float4 v;
            if (EPI) {
                float4 xv = *(const float4*)(xres + (size_t)row * HD + col);
                float4 dv = *(const float4*)(Dp + col);
                v.x = 2.f * acc[i][j + 0] + xv.x * (1.f + dv.x);
                v.y = 2.f * acc[i][j + 1] + xv.y * (1.f + dv.y);
                v.z = 2.f * acc[i][j + 2] + xv.z * (1.f + dv.z);
                v.w = 2.f * acc[i][j + 3] + xv.w * (1.f + dv.w);
            } else {
                v = make_float4(acc[i][j], acc[i][j + 1], acc[i][j + 2], acc[i][j + 3]);
            }
            *(float4*)(C + (size_t)row * N + col) = v;
        }
    }
}

__global__ __launch_bounds__(256) void gemm1_kernel(const float* __restrict__ x)
{
    sgemm_body<false>(x, g_Bbar, g_Bu, HD, N1, nullptr, nullptr);
}

__global__ __launch_bounds__(256) void gemm2_kernel(const float* __restrict__ x,
                                                    const float* __restrict__ D,
                                                    float* __restrict__ out)
{
    sgemm_body<true>(g_xs, g_Cfused, out, N1, HD, x, D);
}

// ---------------- chunked scan ----------------
// phase 1: local end-state per (chunk, channel), zero init
__global__ __launch_bounds__(256) void scan_phase1()
{
    int p = blockIdx.y * blockDim.x + threadIdx.x;
    int c = blockIdx.x;
    float Ar = g_Abar_re[p], Ai = g_Abar_im[p];
    float hr = 0.f, hi = 0.f;
    const float* bu = g_Bu + (size_t)c * CHUNK * N1;
    #pragma unroll 4
    for (int i = 0; i < CHUNK; i++) {
        float br = bu[i * N1 + p];
        float bi = bu[i * N1 + PD + p];
        float nr = fmaf(Ar, hr, fmaf(-Ai, hi, br));
        float ni = fmaf(Ar, hi, fmaf(Ai, hr, bi));
        hr = nr; hi = ni;
    }
    g_E_re[c * PD + p] = hr;
    g_E_im[c * PD + p] = hi;
}

// phase 2: sequential combine across chunks (per channel)
__global__ __launch_bounds__(256) void scan_phase2()
{
    int p = blockIdx.x * blockDim.x + threadIdx.x;
    float Ar = g_AS_re[p], Ai = g_AS_im[p];
    float pr = 0.f, pi = 0.f;
    for (int c = 0; c < NCHUNK; c++) {
        g_pref_re[c * PD + p] = pr;
        g_pref_im[c * PD + p] = pi;
        float er = g_E_re[c * PD + p], ei = g_E_im[c * PD + p];
        float nr = fmaf(Ar, pr, fmaf(-Ai, pi, er));
        float ni = fmaf(Ar, pi, fmaf(Ai, pr, ei));
        pr = nr; pi = ni;
    }
}

// phase 3: re-scan each chunk with the correct initial state, write xs
__global__ __launch_bounds__(256) void scan_phase3()
{
    int p = blockIdx.y * blockDim.x + threadIdx.x;
    int c = blockIdx.x;
    float Ar = g_Abar_re[p], Ai = g_Abar_im[p];
    float hr = g_pref_re[c * PD + p];
    float hi = g_pref_im[c * PD + p];
    const float* bu = g_Bu + (size_t)c * CHUNK * N1;
    float*       xs = g_xs + (size_t)c * CHUNK * N1;
    #pragma unroll 4
    for (int i = 0; i < CHUNK; i++) {
        float br = bu[i * N1 + p];
        float bi = bu[i * N1 + PD + p];
        float nr = fmaf(Ar, hr, fmaf(-Ai, hi, br));
        float ni = fmaf(Ar, hi, fmaf(Ai, hr, bi));
        hr = nr; hi = ni;
        xs[i * N1 + p]      = hr;
        xs[i * N1 + PD + p] = hi;
    }
}

// ---------------- LayerNorm (in place on d_out) ----------------
__global__ __launch_bounds__(256) void ln_kernel(float* __restrict__ out,
                                                 const float* __restrict__ gamma,
                                                 const float* __restrict__ beta)
{
    __shared__ float sh_s[8], sh_s2[8], sh_mr[2];
    int row = blockIdx.x;
    float* r = out + (size_t)row * HD;
    int tid = threadIdx.x;
    float v[4], s = 0.f, s2 = 0.f;
    #pragma unroll
    for (int k = 0; k < 4; k++) {
        v[k] = r[tid + k * 256];
        s += v[k];
        s2 = fmaf(v[k], v[k], s2);
    }
    #pragma unroll
    for (int o = 16; o > 0; o >>= 1) {
        s  += __shfl_down_sync(0xffffffffu, s,  o);
        s2 += __shfl_down_sync(0xffffffffu, s2, o);
    }
    if ((tid & 31) == 0) { sh_s[tid >> 5] = s; sh_s2[tid >> 5] = s2; }
    __syncthreads();
    if (tid == 0) {
        float ts = 0.f, ts2 = 0.f;
        #pragma unroll
        for (int w = 0; w < 8; w++) { ts += sh_s[w]; ts2 += sh_s2[w]; }
        float mean = ts * (1.f / HD);
        float var  = ts2 * (1.f / HD) - mean * mean;
        sh_mr[0] = mean;
        sh_mr[1] = rsqrtf(var + 1e-5f);
    }
    __syncthreads();
    float mean = sh_mr[0], rstd = sh_mr[1];
    #pragma unroll
    for (int k = 0; k < 4; k++) {
        int h = tid + k * 256;
        r[h] = (v[k] - mean) * rstd * gamma[h] + beta[h];
    }
}

// ---------------- launch ----------------
extern "C" void kernel_launch(void* const* d_in, const int* in_sizes, int n_in,
                              void* d_out, int out_size)
{
    const float* x     = (const float*)d_in[0];
    const float* Lre   = (const float*)d_in[1];
    const float* Lim   = (const float*)d_in[2];
    const float* Bre   = (const float*)d_in[3];
    const float* Bim   = (const float*)d_in[4];
    const float* Cre   = (const float*)d_in[5];
    const float* Cim   = (const float*)d_in[6];
    const float* D     = (const float*)d_in[7];
    const float* logdt = (const float*)d_in[8];
    const float* gamma = (const float*)d_in[9];
    const float* beta  = (const float*)d_in[10];
    float* out = (float*)d_out;

    setup_kernel<<<4, 256>>>(Lre, Lim, logdt);
    build_bbar<<<PD * HD / 256, 256>>>(Bre, Bim);
    build_cfused<<<HD * PD / 256, 256>>>(Cre, Cim);

    gemm1_kernel<<<dim3(N1 / 128, LQ / 128), 256>>>(x);           // Bu = x @ Bbar^T

    scan_phase1<<<dim3(NCHUNK, PD / 256), 256>>>();
    scan_phase2<<<PD / 256, 256>>>();
    scan_phase3<<<dim3(NCHUNK, PD / 256), 256>>>();

    gemm2_kernel<<<dim3(HD / 128, LQ / 128), 256>>>(x, D, out);   // y + residual + D-skip

    ln_kernel<<<LQ, 256>>>(out, gamma, beta);
}

// round 6
// speedup vs baseline: 2.3253x; 2.3253x over previous
#include <cuda_runtime.h>
#include <math.h>
#include <stdint.h>

#define LQ 8192
#define HD 1024
#define PD 1024
#define N1 2048
#define NCHUNK 128
#define CHUNK 64

// ---- GEMM tile config ----
#define BM 128
#define BN 128
#define BK 32
#define ASTR 36                         // padded smem row stride (floats)
#define STG (128 * ASTR)                // floats per stage per operand
#define SMEM_FLOATS (4 * STG)           // A0,A1,B0,B1
#define SMEM_BYTES (SMEM_FLOATS * 4)    // 73728

// ---------------- device scratch ----------------
__device__ float g_xt[LQ * HD];          // x, tf32-rounded
__device__ float g_Bbar[N1 * HD];        // (2P,H) tf32-rounded
__device__ float g_Cf[HD * N1];          // (H,2P) tf32-rounded [C_re | -C_im]
__device__ float g_Bu[LQ * N1];          // fp32 scan input
__device__ float g_xs[LQ * N1];          // scan output, tf32-rounded
__device__ float g_Abar_re[PD], g_Abar_im[PD];
__device__ float g_coef_re[PD], g_coef_im[PD];
__device__ float g_AS_re[PD],   g_AS_im[PD];
__device__ float g_E_re[NCHUNK * PD], g_E_im[NCHUNK * PD];
__device__ float g_pref_re[NCHUNK * PD], g_pref_im[NCHUNK * PD];

// ---------------- helpers ----------------
__device__ __forceinline__ float tf32r(float v) {
    uint32_t r;
    asm("cvt.rna.tf32.f32 %0, %1;" : "=r"(r) : "f"(v));
    return __uint_as_float(r);
}
__device__ __forceinline__ uint32_t smem_u32(const void* p) {
    uint32_t a;
    asm("{ .reg .u64 t; cvta.to.shared.u64 t, %1; cvt.u32.u64 %0, t; }" : "=r"(a) : "l"(p));
    return a;
}
__device__ __forceinline__ void cp16(uint32_t saddr, const void* gptr) {
    asm volatile("cp.async.ca.shared.global [%0], [%1], 16;" :: "r"(saddr), "l"(gptr));
}
#define CP_COMMIT() asm volatile("cp.async.commit_group;" ::: "memory")
#define CP_WAIT0()  asm volatile("cp.async.wait_group 0;" ::: "memory")

__device__ __forceinline__ void mma_tf32(float* c, const uint32_t* a, const uint32_t* b) {
    asm volatile("mma.sync.aligned.m16n8k8.row.col.f32.tf32.tf32.f32 "
        "{%0,%1,%2,%3}, {%4,%5,%6,%7}, {%8,%9}, {%0,%1,%2,%3};"
        : "+f"(c[0]), "+f"(c[1]), "+f"(c[2]), "+f"(c[3])
        : "r"(a[0]), "r"(a[1]), "r"(a[2]), "r"(a[3]), "r"(b[0]), "r"(b[1]));
}

// ---------------- setup: discretization (fp64) ----------------
__global__ void setup_kernel(const float* __restrict__ Lre, const float* __restrict__ Lim,
                             const float* __restrict__ logdt)
{
    int p = blockIdx.x * blockDim.x + threadIdx.x;
    if (p >= PD) return;
    double dt  = exp((double)logdt[p]);
    double lr  = (double)Lre[p], li = (double)Lim[p];
    double mag = exp(lr * dt);
    double ang = li * dt;
    double ar  = mag * cos(ang);
    double ai  = mag * sin(ang);
    double den = lr * lr + li * li;
    double cr  = ((ar - 1.0) * lr + ai * li) / den;
    double ci  = (ai * lr - (ar - 1.0) * li) / den;
    g_Abar_re[p] = (float)ar; g_Abar_im[p] = (float)ai;
    g_coef_re[p] = (float)cr; g_coef_im[p] = (float)ci;
    double sr = ar, si = ai;
    #pragma unroll
    for (int i = 0; i < 6; i++) {
        double nr = sr * sr - si * si;
        double ni = 2.0 * sr * si;
        sr = nr; si = ni;
    }
    g_AS_re[p] = (float)sr; g_AS_im[p] = (float)si;
}

__global__ void conv_x(const float* __restrict__ x)
{
    int idx = blockIdx.x * blockDim.x + threadIdx.x;
    if (idx >= LQ * HD) return;
    g_xt[idx] = tf32r(x[idx]);
}

__global__ void build_bbar(const float* __restrict__ Bre, const float* __restrict__ Bim)
{
    int idx = blockIdx.x * blockDim.x + threadIdx.x;
    if (idx >= PD * HD) return;
    int p = idx >> 10;
    float br = Bre[idx], bi = Bim[idx];
    float cr = g_coef_re[p], ci = g_coef_im[p];
    g_Bbar[idx]           = tf32r(cr * br - ci * bi);
    g_Bbar[PD * HD + idx] = tf32r(cr * bi + ci * br);
}

__global__ void build_cfused(const float* __restrict__ Cre, const float* __restrict__ Cim)
{
    int idx = blockIdx.x * blockDim.x + threadIdx.x;
    if (idx >= HD * PD) return;
    int h = idx >> 10, p = idx & (PD - 1);
    g_Cf[h * N1 + p]      = tf32r( Cre[idx]);
    g_Cf[h * N1 + PD + p] = tf32r(-Cim[idx]);
}

// ---------------- mma.sync tf32 GEMM: C[M,CN] = A[M,K] @ B[N,K]^T ----------------
// G1: A=g_xt, B=g_Bbar, C=g_Bu (K=1024, CN=2048, no epilogue)
// !G1: A=g_xs, B=g_Cf, C=out (K=2048, CN=1024, epilogue 2*acc + x*(1+D))
template<int K, bool G1>
__global__ __launch_bounds__(256, 2)
void gemm_mma(float* __restrict__ Cout,
              const float* __restrict__ xres, const float* __restrict__ Dp)
{
    const float* A = G1 ? g_xt : g_xs;
    const float* B = G1 ? g_Bbar : g_Cf;
    float* C = G1 ? g_Bu : Cout;
    const int CN = G1 ? N1 : HD;

    extern __shared__ float sm[];
    const uint32_t sbase = smem_u32(sm);
    const int tid  = threadIdx.x;
    const int wid  = tid >> 5;
    const int lane = tid & 31;
    const int g = lane >> 2, t = lane & 3;
    const int warp_m = (wid & 3) * 32;
    const int warp_n = (wid >> 2) * 64;
    const int bm = blockIdx.y * BM;
    const int bn = blockIdx.x * BN;

    // loader geometry: each thread 4 x 16B per operand per stage
    const int lrow = tid >> 1;
    const int lq0  = (tid & 1) * 4;          // quad 0..7 (each quad = 4 floats)
    const float* Ag = A + (size_t)(bm + lrow) * K + lq0 * 4;
    const float* Bg = B + (size_t)(bn + lrow) * K + lq0 * 4;
    const uint32_t sA = sbase + (lrow * ASTR + lq0 * 4) * 4;
    const uint32_t sB = sbase + (2 * STG + lrow * ASTR + lq0 * 4) * 4;

    float acc[2][8][4];
    #pragma unroll
    for (int i = 0; i < 2; i++)
        #pragma unroll
        for (int j = 0; j < 8; j++)
            #pragma unroll
            for (int q = 0; q < 4; q++) acc[i][j][q] = 0.f;

    constexpr int NCH = K / BK;

    // prologue: load stage 0
    #pragma unroll
    for (int i = 0; i < 4; i++) {
        cp16(sA + i * 16, Ag + i * 4);
        cp16(sB + i * 16, Bg + i * 4);
    }
    CP_COMMIT();

    for (int kc = 0; kc < NCH; kc++) {
        CP_WAIT0();
        __syncthreads();
        const int s = kc & 1;
        if (kc + 1 < NCH) {
            const int ns = s ^ 1;
            const int k0 = (kc + 1) * BK;
            #pragma unroll
            for (int i = 0; i < 4; i++) {
                cp16(sA + ns * STG * 4 + i * 16, Ag + k0 + i * 4);
                cp16(sB + ns * STG * 4 + i * 16, Bg + k0 + i * 4);
            }
            CP_COMMIT();
        }
        const float* As_s = sm + s * STG + (warp_m + g) * ASTR;
        const float* Bs_s = sm + 2 * STG + s * STG + (warp_n + g) * ASTR;
        #pragma unroll
        for (int kk = 0; kk < 4; kk++) {
            const int k = kk * 8 + t;
            uint32_t a[2][4];
            #pragma unroll
            for (int i = 0; i < 2; i++) {
                const float* ap = As_s + i * 16 * ASTR + k;
                a[i][0] = __float_as_uint(ap[0]);
                a[i][1] = __float_as_uint(ap[8 * ASTR]);
                a[i][2] = __float_as_uint(ap[4]);
                a[i][3] = __float_as_uint(ap[8 * ASTR + 4]);
            }
            uint32_t b[8][2];
            #pragma unroll
            for (int j = 0; j < 8; j++) {
                const float* bp = Bs_s + j * 8 * ASTR + k;
                b[j][0] = __float_as_uint(bp[0]);
                b[j][1] = __float_as_uint(bp[4]);
            }
            #pragma unroll
            for (int i = 0; i < 2; i++)
                #pragma unroll
                for (int j = 0; j < 8; j++)
                    mma_tf32(acc[i][j], a[i], b[j]);
        }
        __syncthreads();
    }

    // epilogue: c0,c1 at (row, col..col+1); c2,c3 at (row+8, ...)
    #pragma unroll
    for (int i = 0; i < 2; i++) {
        const int row = bm + warp_m + i * 16 + g;
        #pragma unroll
        for (int j = 0; j < 8; j++) {
            const int col = bn + warp_n + j * 8 + 2 * t;
            float* cp0 = C + (size_t)row * CN + col;
            float* cp1 = C + (size_t)(row + 8) * CN + col;
            if (!G1) {
                const float* xp0 = xres + (size_t)row * HD + col;
                const float* xp1 = xres + (size_t)(row + 8) * HD + col;
                float2 dv = *(const float2*)(Dp + col);
                float2 x0 = *(const float2*)xp0;
                float2 x1 = *(const float2*)xp1;
                float2 v0, v1;
                v0.x = 2.f * acc[i][j][0] + x0.x * (1.f + dv.x);
                v0.y = 2.f * acc[i][j][1] + x0.y * (1.f + dv.y);
                v1.x = 2.f * acc[i][j][2] + x1.x * (1.f + dv.x);
                v1.y = 2.f * acc[i][j][3] + x1.y * (1.f + dv.y);
                *(float2*)cp0 = v0;
                *(float2*)cp1 = v1;
            } else {
                *(float2*)cp0 = make_float2(acc[i][j][0], acc[i][j][1]);
                *(float2*)cp1 = make_float2(acc[i][j][2], acc[i][j][3]);
            }
        }
    }
}

// ---------------- chunked scan ----------------
__global__ __launch_bounds__(256) void scan_phase1()
{
    int p = blockIdx.y * blockDim.x + threadIdx.x;
    int c = blockIdx.x;
    float Ar = g_Abar_re[p], Ai = g_Abar_im[p];
    float hr = 0.f, hi = 0.f;
    const float* bu = g_Bu + (size_t)c * CHUNK * N1;
    #pragma unroll 4
    for (int i = 0; i < CHUNK; i++) {
        float br = bu[i * N1 + p];
        float bi = bu[i * N1 + PD + p];
        float nr = fmaf(Ar, hr, fmaf(-Ai, hi, br));
        float ni = fmaf(Ar, hi, fmaf(Ai, hr, bi));
        hr = nr; hi = ni;
    }
    g_E_re[c * PD + p] = hr;
    g_E_im[c * PD + p] = hi;
}

__global__ __launch_bounds__(256) void scan_phase2()
{
    int p = blockIdx.x * blockDim.x + threadIdx.x;
    float Ar = g_AS_re[p], Ai = g_AS_im[p];
    float pr = 0.f, pi = 0.f;
    for (int c = 0; c < NCHUNK; c++) {
        g_pref_re[c * PD + p] = pr;
        g_pref_im[c * PD + p] = pi;
        float er = g_E_re[c * PD + p], ei = g_E_im[c * PD + p];
        float nr = fmaf(Ar, pr, fmaf(-Ai, pi, er));
        float ni = fmaf(Ar, pi, fmaf(Ai, pr, ei));
        pr = nr; pi = ni;
    }
}

__global__ __launch_bounds__(256) void scan_phase3()
{
    int p = blockIdx.y * blockDim.x + threadIdx.x;
    int c = blockIdx.x;
    float Ar = g_Abar_re[p], Ai = g_Abar_im[p];
    float hr = g_pref_re[c * PD + p];
    float hi = g_pref_im[c * PD + p];
    const float* bu = g_Bu + (size_t)c * CHUNK * N1;
    float*       xs = g_xs + (size_t)c * CHUNK * N1;
    #pragma unroll 4
    for (int i = 0; i < CHUNK; i++) {
        float br = bu[i * N1 + p];
        float bi = bu[i * N1 + PD + p];
        float nr = fmaf(Ar, hr, fmaf(-Ai, hi, br));
        float ni = fmaf(Ar, hi, fmaf(Ai, hr, bi));
        hr = nr; hi = ni;
        xs[i * N1 + p]      = tf32r(hr);
        xs[i * N1 + PD + p] = tf32r(hi);
    }
}

// ---------------- LayerNorm (in place) ----------------
__global__ __launch_bounds__(256) void ln_kernel(float* __restrict__ out,
                                                 const float* __restrict__ gamma,
                                                 const float* __restrict__ beta)
{
    __shared__ float sh_s[8], sh_s2[8], sh_mr[2];
    int row = blockIdx.x;
    float* r = out + (size_t)row * HD;
    int tid = threadIdx.x;
    float v[4], s = 0.f, s2 = 0.f;
    #pragma unroll
    for (int k = 0; k < 4; k++) {
        v[k] = r[tid + k * 256];
        s += v[k];
        s2 = fmaf(v[k], v[k], s2);
    }
    #pragma unroll
    for (int o = 16; o > 0; o >>= 1) {
        s  += __shfl_down_sync(0xffffffffu, s,  o);
        s2 += __shfl_down_sync(0xffffffffu, s2, o);
    }
    if ((tid & 31) == 0) { sh_s[tid >> 5] = s; sh_s2[tid >> 5] = s2; }
    __syncthreads();
    if (tid == 0) {
        float ts = 0.f, ts2 = 0.f;
        #pragma unroll
        for (int w = 0; w < 8; w++) { ts += sh_s[w]; ts2 += sh_s2[w]; }
        float mean = ts * (1.f / HD);
        float var  = ts2 * (1.f / HD) - mean * mean;
        sh_mr[0] = mean;
        sh_mr[1] = rsqrtf(var + 1e-5f);
    }
    __syncthreads();
    float mean = sh_mr[0], rstd = sh_mr[1];
    #pragma unroll
    for (int k = 0; k < 4; k++) {
        int h = tid + k * 256;
        r[h] = (v[k] - mean) * rstd * gamma[h] + beta[h];
    }
}

// ---------------- launch ----------------
extern "C" void kernel_launch(void* const* d_in, const int* in_sizes, int n_in,
                              void* d_out, int out_size)
{
    const float* x     = (const float*)d_in[0];
    const float* Lre   = (const float*)d_in[1];
    const float* Lim   = (const float*)d_in[2];
    const float* Bre   = (const float*)d_in[3];
    const float* Bim   = (const float*)d_in[4];
    const float* Cre   = (const float*)d_in[5];
    const float* Cim   = (const float*)d_in[6];
    const float* D     = (const float*)d_in[7];
    const float* logdt = (const float*)d_in[8];
    const float* gamma = (const float*)d_in[9];
    const float* beta  = (const float*)d_in[10];
    float* out = (float*)d_out;

    cudaFuncSetAttribute(gemm_mma<HD, true>,  cudaFuncAttributeMaxDynamicSharedMemorySize, SMEM_BYTES);
    cudaFuncSetAttribute(gemm_mma<N1, false>, cudaFuncAttributeMaxDynamicSharedMemorySize, SMEM_BYTES);

    setup_kernel<<<4, 256>>>(Lre, Lim, logdt);
    conv_x<<<LQ * HD / 256, 256>>>(x);
    build_bbar<<<PD * HD / 256, 256>>>(Bre, Bim);
    build_cfused<<<HD * PD / 256, 256>>>(Cre, Cim);

    // Bu = x @ Bbar^T   (M=8192, N=2048, K=1024)
    gemm_mma<HD, true><<<dim3(N1 / BN, LQ / BM), 256, SMEM_BYTES>>>(nullptr, nullptr, nullptr);

    scan_phase1<<<dim3(NCHUNK, PD / 256), 256>>>();
    scan_phase2<<<PD / 256, 256>>>();
    scan_phase3<<<dim3(NCHUNK, PD / 256), 256>>>();

    // out = 2*Re(xs @ C^T) + x*(1+D)   (M=8192, N=1024, K=2048)
    gemm_mma<N1, false><<<dim3(HD / BN, LQ / BM), 256, SMEM_BYTES>>>(out, x, D);

    ln_kernel<<<LQ, 256>>>(out, gamma, beta);
}

// round 7
// speedup vs baseline: 3.4451x; 1.4815x over previous
#include <cuda_runtime.h>
#include <math.h>
#include <stdint.h>

#define LQ 8192
#define HD 1024
#define PD 1024
#define N1 2048
#define NCHUNK 128
#define CHUNK 64

// ---- GEMM tile config ----
#define BM 128
#define BN 256
#define BK 32
#define NST 3
#define ASTR 36                          // padded smem row stride (floats)
#define ASTG (128 * ASTR)                // A floats per stage
#define BSTG (256 * ASTR)                // B floats per stage
#define STGF (ASTG + BSTG)               // floats per stage
#define SMEM_BYTES (NST * STGF * 4)      // 165888

// ---------------- device scratch ----------------
__device__ float g_Bbar[N1 * HD];        // (2P,H) tf32-rounded
__device__ float g_Cf[HD * N1];          // (H,2P) tf32-rounded [C_re | -C_im]
__device__ float g_Bu[LQ * N1];          // fp32 scan input
__device__ float g_xs[LQ * N1];          // scan output, tf32-rounded
__device__ float g_Abar_re[PD], g_Abar_im[PD];
__device__ float g_coef_re[PD], g_coef_im[PD];
__device__ float g_AS_re[PD],   g_AS_im[PD];
__device__ float g_E_re[NCHUNK * PD], g_E_im[NCHUNK * PD];
__device__ float g_pref_re[NCHUNK * PD], g_pref_im[NCHUNK * PD];

// ---------------- helpers ----------------
__device__ __forceinline__ float tf32r(float v) {
    uint32_t r;
    asm("cvt.rna.tf32.f32 %0, %1;" : "=r"(r) : "f"(v));
    return __uint_as_float(r);
}
__device__ __forceinline__ uint32_t smem_u32(const void* p) {
    uint32_t a;
    asm("{ .reg .u64 t; cvta.to.shared.u64 t, %1; cvt.u32.u64 %0, t; }" : "=r"(a) : "l"(p));
    return a;
}
__device__ __forceinline__ void cp16(uint32_t saddr, const void* gptr) {
    asm volatile("cp.async.ca.shared.global [%0], [%1], 16;" :: "r"(saddr), "l"(gptr));
}
#define CP_COMMIT() asm volatile("cp.async.commit_group;" ::: "memory")
#define CP_WAIT1()  asm volatile("cp.async.wait_group 1;" ::: "memory")

__device__ __forceinline__ void mma_tf32(float* c, const uint32_t* a, const uint32_t* b) {
    asm volatile("mma.sync.aligned.m16n8k8.row.col.f32.tf32.tf32.f32 "
        "{%0,%1,%2,%3}, {%4,%5,%6,%7}, {%8,%9}, {%0,%1,%2,%3};"
        : "+f"(c[0]), "+f"(c[1]), "+f"(c[2]), "+f"(c[3])
        : "r"(a[0]), "r"(a[1]), "r"(a[2]), "r"(a[3]), "r"(b[0]), "r"(b[1]));
}

// ---------------- setup: discretization (fp64) ----------------
__global__ void setup_kernel(const float* __restrict__ Lre, const float* __restrict__ Lim,
                             const float* __restrict__ logdt)
{
    int p = blockIdx.x * blockDim.x + threadIdx.x;
    if (p >= PD) return;
    double dt  = exp((double)logdt[p]);
    double lr  = (double)Lre[p], li = (double)Lim[p];
    double mag = exp(lr * dt);
    double ang = li * dt;
    double ar  = mag * cos(ang);
    double ai  = mag * sin(ang);
    double den = lr * lr + li * li;
    double cr  = ((ar - 1.0) * lr + ai * li) / den;
    double ci  = (ai * lr - (ar - 1.0) * li) / den;
    g_Abar_re[p] = (float)ar; g_Abar_im[p] = (float)ai;
    g_coef_re[p] = (float)cr; g_coef_im[p] = (float)ci;
    double sr = ar, si = ai;
    #pragma unroll
    for (int i = 0; i < 6; i++) {
        double nr = sr * sr - si * si;
        double ni = 2.0 * sr * si;
        sr = nr; si = ni;
    }
    g_AS_re[p] = (float)sr; g_AS_im[p] = (float)si;
}

__global__ void build_bbar(const float* __restrict__ Bre, const float* __restrict__ Bim)
{
    int idx = blockIdx.x * blockDim.x + threadIdx.x;
    if (idx >= PD * HD) return;
    int p = idx >> 10;
    float br = Bre[idx], bi = Bim[idx];
    float cr = g_coef_re[p], ci = g_coef_im[p];
    g_Bbar[idx]           = tf32r(cr * br - ci * bi);
    g_Bbar[PD * HD + idx] = tf32r(cr * bi + ci * br);
}

__global__ void build_cfused(const float* __restrict__ Cre, const float* __restrict__ Cim)
{
    int idx = blockIdx.x * blockDim.x + threadIdx.x;
    if (idx >= HD * PD) return;
    int h = idx >> 10, p = idx & (PD - 1);
    g_Cf[h * N1 + p]      = tf32r( Cre[idx]);
    g_Cf[h * N1 + PD + p] = tf32r(-Cim[idx]);
}

// ---------------- mma.sync tf32 GEMM: C[M,CN] = A[M,K] @ B[N,K]^T ----------------
// BM=128, BN=256, BK=32, 3-stage cp.async, warp tile 64x64 (2x4 warps)
// G1: A=x (raw fp32, HW-truncated), B=g_Bbar, C=g_Bu (no epilogue)
// !G1: A=g_xs, B=g_Cf, C=out (epilogue 2*acc + x*(1+D))
template<int K, bool G1>
__global__ __launch_bounds__(256)
void gemm_mma(const float* __restrict__ A, float* __restrict__ Cout,
              const float* __restrict__ xres, const float* __restrict__ Dp)
{
    const float* B = G1 ? g_Bbar : g_Cf;
    float* C = G1 ? g_Bu : Cout;
    const int CN = G1 ? N1 : HD;

    extern __shared__ float sm[];
    const uint32_t sbase = smem_u32(sm);
    const int tid  = threadIdx.x;
    const int wid  = tid >> 5;
    const int lane = tid & 31;
    const int g = lane >> 2, t = lane & 3;
    const int warp_m = (wid & 1) * 64;
    const int warp_n = (wid >> 1) * 64;
    const int bm = blockIdx.y * BM;
    const int bn = blockIdx.x * BN;

    // loader geometry: rows arow + i*32, quad aq
    const int arow = tid >> 3;
    const int aq   = (tid & 7) * 4;
    const float* Ag = A + (size_t)(bm + arow) * K + aq;
    const float* Bg = B + (size_t)(bn + arow) * K + aq;
    const uint32_t sAo = (uint32_t)(arow * ASTR + aq) * 4;

    float acc[4][8][4];
    #pragma unroll
    for (int i = 0; i < 4; i++)
        #pragma unroll
        for (int j = 0; j < 8; j++)
            #pragma unroll
            for (int q = 0; q < 4; q++) acc[i][j][q] = 0.f;

    constexpr int NCH = K / BK;

    auto load_stage = [&](int st, int k0) {
        const uint32_t sa = sbase + (uint32_t)(st * STGF * 4) + sAo;
        const uint32_t sb = sa + (uint32_t)(ASTG * 4);
        #pragma unroll
        for (int i = 0; i < 4; i++)
            cp16(sa + i * 32 * ASTR * 4, Ag + k0 + (size_t)i * 32 * K);
        #pragma unroll
        for (int i = 0; i < 8; i++)
            cp16(sb + i * 32 * ASTR * 4, Bg + k0 + (size_t)i * 32 * K);
    };

    load_stage(0, 0);  CP_COMMIT();
    load_stage(1, BK); CP_COMMIT();

    for (int kc = 0; kc < NCH; kc++) {
        CP_WAIT1();
        __syncthreads();
        if (kc + 2 < NCH) load_stage((kc + 2) % NST, (kc + 2) * BK);
        CP_COMMIT();

        const int st = kc % NST;
        const float* As_s = sm + st * STGF + (warp_m + g) * ASTR;
        const float* Bs_s = sm + st * STGF + ASTG + (warp_n + g) * ASTR;
        #pragma unroll
        for (int kk = 0; kk < 4; kk++) {
            const int k = kk * 8 + t;
            uint32_t a[4][4];
            #pragma unroll
            for (int i = 0; i < 4; i++) {
                const float* ap = As_s + i * 16 * ASTR + k;
                a[i][0] = __float_as_uint(ap[0]);
                a[i][1] = __float_as_uint(ap[8 * ASTR]);
                a[i][2] = __float_as_uint(ap[4]);
                a[i][3] = __float_as_uint(ap[8 * ASTR + 4]);
            }
            uint32_t b[8][2];
            #pragma unroll
            for (int j = 0; j < 8; j++) {
                const float* bp = Bs_s + j * 8 * ASTR + k;
                b[j][0] = __float_as_uint(bp[0]);
                b[j][1] = __float_as_uint(bp[4]);
            }
            #pragma unroll
            for (int i = 0; i < 4; i++)
                #pragma unroll
                for (int j = 0; j < 8; j++)
                    mma_tf32(acc[i][j], a[i], b[j]);
        }
    }

    // epilogue: c0,c1 at (row, col..col+1); c2,c3 at (row+8, ...)
    #pragma unroll
    for (int i = 0; i < 4; i++) {
        const int row = bm + warp_m + i * 16 + g;
        #pragma unroll
        for (int j = 0; j < 8; j++) {
            const int col = bn + warp_n + j * 8 + 2 * t;
            float* cp0 = C + (size_t)row * CN + col;
            float* cp1 = C + (size_t)(row + 8) * CN + col;
            if (!G1) {
                const float* xp0 = xres + (size_t)row * HD + col;
                const float* xp1 = xres + (size_t)(row + 8) * HD + col;
                float2 dv = *(const float2*)(Dp + col);
                float2 x0 = *(const float2*)xp0;
                float2 x1 = *(const float2*)xp1;
                float2 v0, v1;
                v0.x = 2.f * acc[i][j][0] + x0.x * (1.f + dv.x);
                v0.y = 2.f * acc[i][j][1] + x0.y * (1.f + dv.y);
                v1.x = 2.f * acc[i][j][2] + x1.x * (1.f + dv.x);
                v1.y = 2.f * acc[i][j][3] + x1.y * (1.f + dv.y);
                *(float2*)cp0 = v0;
                *(float2*)cp1 = v1;
            } else {
                *(float2*)cp0 = make_float2(acc[i][j][0], acc[i][j][1]);
                *(float2*)cp1 = make_float2(acc[i][j][2], acc[i][j][3]);
            }
        }
    }
}

// ---------------- chunked scan ----------------
__global__ __launch_bounds__(256) void scan_phase1()
{
    int p = blockIdx.y * blockDim.x + threadIdx.x;
    int c = blockIdx.x;
    float Ar = g_Abar_re[p], Ai = g_Abar_im[p];
    float hr = 0.f, hi = 0.f;
    const float* bu = g_Bu + (size_t)c * CHUNK * N1;
    #pragma unroll 4
    for (int i = 0; i < CHUNK; i++) {
        float br = bu[i * N1 + p];
        float bi = bu[i * N1 + PD + p];
        float nr = fmaf(Ar, hr, fmaf(-Ai, hi, br));
        float ni = fmaf(Ar, hi, fmaf(Ai, hr, bi));
        hr = nr; hi = ni;
    }
    g_E_re[c * PD + p] = hr;
    g_E_im[c * PD + p] = hi;
}

__global__ __launch_bounds__(256) void scan_phase2()
{
    int p = blockIdx.x * blockDim.x + threadIdx.x;
    float Ar = g_AS_re[p], Ai = g_AS_im[p];
    float pr = 0.f, pi = 0.f;
    for (int c = 0; c < NCHUNK; c++) {
        g_pref_re[c * PD + p] = pr;
        g_pref_im[c * PD + p] = pi;
        float er = g_E_re[c * PD + p], ei = g_E_im[c * PD + p];
        float nr = fmaf(Ar, pr, fmaf(-Ai, pi, er));
        float ni = fmaf(Ar, pi, fmaf(Ai, pr, ei));
        pr = nr; pi = ni;
    }
}

__global__ __launch_bounds__(256) void scan_phase3()
{
    int p = blockIdx.y * blockDim.x + threadIdx.x;
    int c = blockIdx.x;
    float Ar = g_Abar_re[p], Ai = g_Abar_im[p];
    float hr = g_pref_re[c * PD + p];
    float hi = g_pref_im[c * PD + p];
    const float* bu = g_Bu + (size_t)c * CHUNK * N1;
    float*       xs = g_xs + (size_t)c * CHUNK * N1;
    #pragma unroll 4
    for (int i = 0; i < CHUNK; i++) {
        float br = bu[i * N1 + p];
        float bi = bu[i * N1 + PD + p];
        float nr = fmaf(Ar, hr, fmaf(-Ai, hi, br));
        float ni = fmaf(Ar, hi, fmaf(Ai, hr, bi));
        hr = nr; hi = ni;
        xs[i * N1 + p]      = tf32r(hr);
        xs[i * N1 + PD + p] = tf32r(hi);
    }
}

// ---------------- LayerNorm (in place) ----------------
__global__ __launch_bounds__(256) void ln_kernel(float* __restrict__ out,
                                                 const float* __restrict__ gamma,
                                                 const float* __restrict__ beta)
{
    __shared__ float sh_s[8], sh_s2[8], sh_mr[2];
    int row = blockIdx.x;
    float* r = out + (size_t)row * HD;
    int tid = threadIdx.x;
    float v[4], s = 0.f, s2 = 0.f;
    #pragma unroll
    for (int k = 0; k < 4; k++) {
        v[k] = r[tid + k * 256];
        s += v[k];
        s2 = fmaf(v[k], v[k], s2);
    }
    #pragma unroll
    for (int o = 16; o > 0; o >>= 1) {
        s  += __shfl_down_sync(0xffffffffu, s,  o);
        s2 += __shfl_down_sync(0xffffffffu, s2, o);
    }
    if ((tid & 31) == 0) { sh_s[tid >> 5] = s; sh_s2[tid >> 5] = s2; }
    __syncthreads();
    if (tid == 0) {
        float ts = 0.f, ts2 = 0.f;
        #pragma unroll
        for (int w = 0; w < 8; w++) { ts += sh_s[w]; ts2 += sh_s2[w]; }
        float mean = ts * (1.f / HD);
        float var  = ts2 * (1.f / HD) - mean * mean;
        sh_mr[0] = mean;
        sh_mr[1] = rsqrtf(var + 1e-5f);
    }
    __syncthreads();
    float mean = sh_mr[0], rstd = sh_mr[1];
    #pragma unroll
    for (int k = 0; k < 4; k++) {
        int h = tid + k * 256;
        r[h] = (v[k] - mean) * rstd * gamma[h] + beta[h];
    }
}

// ---------------- launch ----------------
extern "C" void kernel_launch(void* const* d_in, const int* in_sizes, int n_in,
                              void* d_out, int out_size)
{
    const float* x     = (const float*)d_in[0];
    const float* Lre   = (const float*)d_in[1];
    const float* Lim   = (const float*)d_in[2];
    const float* Bre   = (const float*)d_in[3];
    const float* Bim   = (const float*)d_in[4];
    const float* Cre   = (const float*)d_in[5];
    const float* Cim   = (const float*)d_in[6];
    const float* D     = (const float*)d_in[7];
    const float* logdt = (const float*)d_in[8];
    const float* gamma = (const float*)d_in[9];
    const float* beta  = (const float*)d_in[10];
    float* out = (float*)d_out;

    cudaFuncSetAttribute(gemm_mma<HD, true>,  cudaFuncAttributeMaxDynamicSharedMemorySize, SMEM_BYTES);
    cudaFuncSetAttribute(gemm_mma<N1, false>, cudaFuncAttributeMaxDynamicSharedMemorySize, SMEM_BYTES);

    setup_kernel<<<4, 256>>>(Lre, Lim, logdt);
    build_bbar<<<PD * HD / 256, 256>>>(Bre, Bim);
    build_cfused<<<HD * PD / 256, 256>>>(Cre, Cim);

    // Bu = x @ Bbar^T   (M=8192, N=2048, K=1024)
    gemm_mma<HD, true><<<dim3(N1 / BN, LQ / BM), 256, SMEM_BYTES>>>(x, nullptr, nullptr, nullptr);

    scan_phase1<<<dim3(NCHUNK, PD / 256), 256>>>();
    scan_phase2<<<PD / 256, 256>>>();
    scan_phase3<<<dim3(NCHUNK, PD / 256), 256>>>();

    // out = 2*Re(xs @ C^T) + x*(1+D)   (M=8192, N=1024, K=2048)
    float* xs_ptr = nullptr;
    cudaGetSymbolAddress((void**)&xs_ptr, g_xs);
    gemm_mma<N1, false><<<dim3(HD / BN, LQ / BM), 256, SMEM_BYTES>>>(xs_ptr, out, x, D);

    ln_kernel<<<LQ, 256>>>(out, gamma, beta);
}